// round 4
// baseline (speedup 1.0000x reference)
#include <cuda_runtime.h>
#include <cuda_bf16.h>

#define MAX_ROWS 8192
__device__ double g_row_loss[MAX_ROWS];
__device__ unsigned int g_done = 0;   // self-resets each run -> graph-replay safe

__device__ __forceinline__ float ex2(float x) {
    float y;
    asm("ex2.approx.f32 %0, %1;" : "=f"(y) : "f"(x));
    return y;
}

// One block per row. Software-pipelined stream: next group of 4 LDG.128 is
// issued BEFORE consuming the current group, so loads stay in flight during
// the FMUL/MUFU/FADD phase (the R3 kernel had zero loads outstanding there).
__global__ void __launch_bounds__(256, 4) cosarc_fused_kernel(
    const float* __restrict__ preds,
    const int* __restrict__ labels,     // int32 (JAX x64 disabled)
    float* __restrict__ out,
    int V, int B)
{
    const int row = blockIdx.x;
    const float* rp = preds + (size_t)row * (size_t)V;
    const float4* p4 = reinterpret_cast<const float4*>(rp);
    const int n4 = V >> 2;
    const int s = 256;

    // exp(30*x) = exp2(x * 30*log2(e))
    const float C = 30.0f * 1.4426950408889634f;

    float s0 = 0.f, s1 = 0.f, s2 = 0.f, s3 = 0.f;
    int i = threadIdx.x;

    float4 a0, a1, a2, a3;
    const bool have = (i + 3 * s < n4);
    if (have) {
        a0 = __ldg(&p4[i]);
        a1 = __ldg(&p4[i + s]);
        a2 = __ldg(&p4[i + 2 * s]);
        a3 = __ldg(&p4[i + 3 * s]);
    }

    // Steady state: issue next 4 loads, then consume previous 4.
    for (; i + 7 * s < n4; i += 4 * s) {
        float4 b0 = __ldg(&p4[i + 4 * s]);
        float4 b1 = __ldg(&p4[i + 5 * s]);
        float4 b2 = __ldg(&p4[i + 6 * s]);
        float4 b3 = __ldg(&p4[i + 7 * s]);
        s0 += ex2(a0.x * C) + ex2(a0.y * C) + ex2(a0.z * C) + ex2(a0.w * C);
        s1 += ex2(a1.x * C) + ex2(a1.y * C) + ex2(a1.z * C) + ex2(a1.w * C);
        s2 += ex2(a2.x * C) + ex2(a2.y * C) + ex2(a2.z * C) + ex2(a2.w * C);
        s3 += ex2(a3.x * C) + ex2(a3.y * C) + ex2(a3.z * C) + ex2(a3.w * C);
        a0 = b0; a1 = b1; a2 = b2; a3 = b3;
    }
    if (have) {
        s0 += ex2(a0.x * C) + ex2(a0.y * C) + ex2(a0.z * C) + ex2(a0.w * C);
        s1 += ex2(a1.x * C) + ex2(a1.y * C) + ex2(a1.z * C) + ex2(a1.w * C);
        s2 += ex2(a2.x * C) + ex2(a2.y * C) + ex2(a2.z * C) + ex2(a2.w * C);
        s3 += ex2(a3.x * C) + ex2(a3.y * C) + ex2(a3.z * C) + ex2(a3.w * C);
        i += 4 * s;
    }
    // Remainder float4s (per-thread count is 31 or 32 for V=32000).
    for (; i < n4; i += s) {
        float4 a = __ldg(&p4[i]);
        s0 += ex2(a.x * C) + ex2(a.y * C) + ex2(a.z * C) + ex2(a.w * C);
    }
    // Scalar tail (V % 4) — not hit for V=32000.
    for (int j = (n4 << 2) + threadIdx.x; j < V; j += s)
        s0 += ex2(rp[j] * C);

    float sum = (s0 + s1) + (s2 + s3);

    #pragma unroll
    for (int o = 16; o > 0; o >>= 1)
        sum += __shfl_xor_sync(0xffffffffu, sum, o);

    __shared__ float warpsum[8];
    const int wid = threadIdx.x >> 5;
    const int lid = threadIdx.x & 31;
    if (lid == 0) warpsum[wid] = sum;
    __syncthreads();

    if (threadIdx.x == 0) {
        float tot = 0.f;
        #pragma unroll
        for (int w = 0; w < 8; w++) tot += warpsum[w];

        int lab = labels[row];
        if (lab < 0) lab = 0;
        if (lab >= V) lab = V - 1;
        const float target = rp[lab];

        double sum_others = (double)tot - (double)ex2(target * C);

        const double EPS = 1e-12;
        const double PI  = 3.14159265358979323846;
        double t = (double)target;
        t = fmin(fmax(t, -1.0 + EPS), 1.0 - EPS);
        double theta = acos(t);
        theta = fmin(fmax(theta, EPS), PI - EPS);
        double numerator = 30.0 * (cos(theta + 0.5) - 0.35);
        double denominator = exp(numerator) + sum_others;
        g_row_loss[row] = numerator - log(denominator);
    }

    // ---- last-block-done final reduction (deterministic fixed-order sum) ----
    __threadfence();
    __shared__ bool is_last;
    if (threadIdx.x == 0)
        is_last = (atomicAdd(&g_done, 1u) == (unsigned)(gridDim.x - 1));
    __syncthreads();

    if (is_last) {
        double d = 0.0;
        for (int j = threadIdx.x; j < B; j += s)
            d += g_row_loss[j];

        #pragma unroll
        for (int o = 16; o > 0; o >>= 1)
            d += __shfl_xor_sync(0xffffffffu, d, o);

        __shared__ double dwarp[8];
        if (lid == 0) dwarp[wid] = d;
        __syncthreads();

        if (threadIdx.x == 0) {
            double tot = 0.0;
            #pragma unroll
            for (int w = 0; w < 8; w++) tot += dwarp[w];
            out[0] = (float)(-tot / (double)B);
            g_done = 0;   // reset for next graph replay
        }
    }
}

extern "C" void kernel_launch(void* const* d_in, const int* in_sizes, int n_in,
                              void* d_out, int out_size)
{
    const float* preds  = (const float*)d_in[0];
    const int*   labels = (const int*)d_in[1];

    const int B = in_sizes[1];                 // 2048
    const int V = in_sizes[0] / B;             // 32000

    cosarc_fused_kernel<<<B, 256>>>(preds, labels, (float*)d_out, V, B);
}

// round 5
// speedup vs baseline: 1.1836x; 1.1836x over previous
#include <cuda_runtime.h>
#include <cuda_bf16.h>

#define MAX_ROWS 8192
#define STAGES 4      // cp.async pipeline depth (groups in flight)
#define NSLOTS 6      // SMEM ring slots (> STAGES+1: safe WAR reuse distance)

__device__ double g_row_loss[MAX_ROWS];
__device__ unsigned int g_done = 0;   // self-resets each run -> graph-replay safe

__device__ __forceinline__ float ex2(float x) {
    float y;
    asm("ex2.approx.f32 %0, %1;" : "=f"(y) : "f"(x));
    return y;
}

// One block (256 thr) per row. Each thread streams its own 16B/chunk through a
// per-thread SMEM ring via cp.async: depth-4 fire-and-forget keeps ~2KB/warp of
// loads in flight during the exp phase WITHOUT burning registers (R4 lesson),
// so occupancy stays at 8 blocks/SM. No __syncthreads in the hot loop: every
// thread consumes only the slot it filled itself.
__global__ void __launch_bounds__(256) cosarc_fused_kernel(
    const float* __restrict__ preds,
    const int* __restrict__ labels,     // int32 (JAX x64 disabled)
    float* __restrict__ out,
    int V, int B)
{
    __shared__ float4 buf[NSLOTS][256];

    const int tid = threadIdx.x;
    const int wid = tid >> 5;
    const int lid = tid & 31;
    const int row = blockIdx.x;
    const float* rp = preds + (size_t)row * (size_t)V;
    const float4* p4 = reinterpret_cast<const float4*>(rp);
    const int n4 = V >> 2;

    // Per-warp contiguous range of float4s (8 warps/block): coalesced 512B chunks.
    const int start = (int)(((long long)n4 * wid) >> 3);
    const int end   = (int)(((long long)n4 * (wid + 1)) >> 3);
    const int chunks = (end - start + 31) >> 5;

    const float C = 30.0f * 1.4426950408889634f;   // exp(30x) = exp2(C*x)
    float s0 = 0.f, s1 = 0.f;

    // Prologue: issue chunks 0..STAGES-1 (predicated per-lane), one group each.
    #pragma unroll
    for (int s = 0; s < STAGES; s++) {
        int g = start + s * 32 + lid;
        if (s < chunks && g < end) {
            unsigned int dst = (unsigned int)__cvta_generic_to_shared(&buf[s % NSLOTS][tid]);
            asm volatile("cp.async.cg.shared.global [%0], [%1], 16;"
                         :: "r"(dst), "l"(p4 + g) : "memory");
        }
        asm volatile("cp.async.commit_group;" ::: "memory");
    }

    for (int c = 0; c < chunks; c++) {
        // Wait until <= STAGES-1 groups pending -> chunk c's group is done.
        asm volatile("cp.async.wait_group %0;" :: "n"(STAGES - 1) : "memory");

        int g = start + c * 32 + lid;
        if (g < end) {
            float4 v = buf[c % NSLOTS][tid];
            s0 += ex2(v.x * C) + ex2(v.y * C);
            s1 += ex2(v.z * C) + ex2(v.w * C);
        }

        // Issue chunk c+STAGES into a slot whose previous tenant (c+STAGES-NSLOTS)
        // was consumed >= 2 iterations ago (wait_group in between) -> no WAR.
        int nc = c + STAGES;
        int gn = start + nc * 32 + lid;
        if (nc < chunks && gn < end) {
            unsigned int dst = (unsigned int)__cvta_generic_to_shared(&buf[nc % NSLOTS][tid]);
            asm volatile("cp.async.cg.shared.global [%0], [%1], 16;"
                         :: "r"(dst), "l"(p4 + gn) : "memory");
        }
        asm volatile("cp.async.commit_group;" ::: "memory");
    }
    // Scalar tail (V % 4 != 0) — not hit for V=32000.
    for (int j = (n4 << 2) + tid; j < V; j += 256)
        s0 += ex2(rp[j] * C);

    float sum = s0 + s1;

    #pragma unroll
    for (int o = 16; o > 0; o >>= 1)
        sum += __shfl_xor_sync(0xffffffffu, sum, o);

    __shared__ float warpsum[8];
    if (lid == 0) warpsum[wid] = sum;
    __syncthreads();

    if (tid == 0) {
        float tot = 0.f;
        #pragma unroll
        for (int w = 0; w < 8; w++) tot += warpsum[w];

        int lab = labels[row];
        if (lab < 0) lab = 0;
        if (lab >= V) lab = V - 1;
        const float target = rp[lab];

        double sum_others = (double)tot - (double)ex2(target * C);

        const double EPS = 1e-12;
        const double PI  = 3.14159265358979323846;
        double t = (double)target;
        t = fmin(fmax(t, -1.0 + EPS), 1.0 - EPS);
        double theta = acos(t);
        theta = fmin(fmax(theta, EPS), PI - EPS);
        double numerator = 30.0 * (cos(theta + 0.5) - 0.35);
        double denominator = exp(numerator) + sum_others;
        g_row_loss[row] = numerator - log(denominator);
    }

    // ---- last-block-done final reduction (deterministic fixed-order sum) ----
    __threadfence();
    __shared__ bool is_last;
    if (tid == 0)
        is_last = (atomicAdd(&g_done, 1u) == (unsigned)(gridDim.x - 1));
    __syncthreads();

    if (is_last) {
        double d = 0.0;
        for (int j = tid; j < B; j += 256)
            d += g_row_loss[j];

        #pragma unroll
        for (int o = 16; o > 0; o >>= 1)
            d += __shfl_xor_sync(0xffffffffu, d, o);

        __shared__ double dwarp[8];
        if (lid == 0) dwarp[wid] = d;
        __syncthreads();

        if (tid == 0) {
            double tot = 0.0;
            #pragma unroll
            for (int w = 0; w < 8; w++) tot += dwarp[w];
            out[0] = (float)(-tot / (double)B);
            g_done = 0;   // reset for next graph replay
        }
    }
}

extern "C" void kernel_launch(void* const* d_in, const int* in_sizes, int n_in,
                              void* d_out, int out_size)
{
    const float* preds  = (const float*)d_in[0];
    const int*   labels = (const int*)d_in[1];

    const int B = in_sizes[1];                 // 2048
    const int V = in_sizes[0] / B;             // 32000

    cosarc_fused_kernel<<<B, 256>>>(preds, labels, (float*)d_out, V, B);
}